// round 7
// baseline (speedup 1.0000x reference)
#include <cuda_runtime.h>
#include <cuda_bf16.h>

using u32 = unsigned int;
using u64 = unsigned long long;

// Problem constants (fixed by setup_inputs)
constexpr int B = 4, S = 4096, D = 256, M = 256, H = 8;
constexpr int SK = 16;                  // split-K chunks for ctx GEMM
constexpr float LNEPS = 1e-5f;
constexpr float KEPS  = 1e-4f;
constexpr float DN    = 0.25f;          // 256^-0.25
constexpr float RATIO = 0.0625f;        // 256^-0.5

// ---------------- device scratch (no allocation APIs allowed) --------------
__device__ float g_xn[B * S * D];                 // layernormed x (= v), fp32
__device__ float g_diag[B * S];
__device__ __nv_bfloat16 g_ah[B * S * D], g_al[B * S * D];   // split(DN*xn) [s,d]
__device__ __nv_bfloat16 g_pbh[M * D],   g_pbl[M * D];       // split(proj)  [m,d]
__device__ __nv_bfloat16 g_vth[B * D * S], g_vtl[B * D * S]; // split(xn^T)  [d,s]
__device__ float g_pd[B * S * M];                 // projection, fp32
__device__ float g_pmax[B * S * 2];               // row-max partials (2 m-tiles)
__device__ float g_rowmax[B * S];
__device__ float g_bmax[B];
__device__ __nv_bfloat16 g_qh[B * S * M], g_ql[B * S * M];   // split(q)  [s,m]
__device__ __nv_bfloat16 g_kth[B * M * S], g_ktl[B * M * S]; // split(k^T)[m,s]
__device__ float g_pksum[B * (S / 32) * M];
__device__ float g_ksum[B * M];
__device__ float g_pctx[B * SK * M * D];          // split-K ctx partials
__device__ __nv_bfloat16 g_cth[B * D * M], g_ctl[B * D * M]; // split(ctx^T)[d,m]
__device__ float g_dinv[B * S];

// ---------------- PTX helpers (plain sm_103-safe: mma.sync/ldmatrix/cp.async)
__device__ __forceinline__ u32 s2u(const void* p) {
    u32 a;
    asm("{ .reg .u64 t; cvta.to.shared.u64 t, %1; cvt.u32.u64 %0, t; }"
        : "=r"(a) : "l"(p));
    return a;
}
#define LDM4(r, a) \
    asm volatile("ldmatrix.sync.aligned.m8n8.x4.shared.b16 {%0,%1,%2,%3}, [%4];" \
        : "=r"((r)[0]), "=r"((r)[1]), "=r"((r)[2]), "=r"((r)[3]) : "r"(a))
#define MMA(c, a, b0_, b1_) \
    asm volatile("mma.sync.aligned.m16n8k16.row.col.f32.bf16.bf16.f32 " \
        "{%0,%1,%2,%3}, {%4,%5,%6,%7}, {%8,%9}, {%0,%1,%2,%3};" \
        : "+f"((c)[0]), "+f"((c)[1]), "+f"((c)[2]), "+f"((c)[3]) \
        : "r"((a)[0]), "r"((a)[1]), "r"((a)[2]), "r"((a)[3]), "r"(b0_), "r"(b1_))
#define CP_ASYNC16(dst, src) \
    asm volatile("cp.async.cg.shared.global [%0], [%1], 16;" :: "r"(dst), "l"(src))
#define CP_COMMIT() asm volatile("cp.async.commit_group;" ::: "memory")

// smem stage geometry: 4 tiles (Ah,Al,Bh,Bl) of 128 rows x 64 bf16, padded to
// 144B/row (conflict-free ldmatrix), double buffered.
constexpr int TROW   = 144;                 // bytes per padded row
constexpr int TILEB  = 128 * TROW;          // 18432 B per tile
constexpr int STAGEB = 4 * TILEB;           // 73728 B per stage
constexpr int SMEM_MMA = 2 * STAGEB;        // 147456 B
constexpr int NPAD = 132;                   // epilogue fp32 row stride (528 B)

__device__ __forceinline__ void split_store(__nv_bfloat16* hi, __nv_bfloat16* lo,
                                            size_t o, float v) {
    __nv_bfloat16 h = __float2bfloat16(v);
    hi[o] = h;
    lo[o] = __float2bfloat16(v - __bfloat162float(h));
}

// ============================================================
// K1: LayerNorm + diag + bf16 split of DN*xn
// ============================================================
__global__ void __launch_bounds__(256) k_ln(const float* __restrict__ x,
                                            const float* __restrict__ gamma,
                                            const float* __restrict__ beta) {
    const int row = blockIdx.x;            // b*S + s
    const int t = threadIdx.x;
    const float v = x[(size_t)row * D + t];
    __shared__ float s1[8], s2[8];
    float a = v, b2 = v * v;
#pragma unroll
    for (int o = 16; o; o >>= 1) {
        a  += __shfl_down_sync(~0u, a, o);
        b2 += __shfl_down_sync(~0u, b2, o);
    }
    if ((t & 31) == 0) { s1[t >> 5] = a; s2[t >> 5] = b2; }
    __syncthreads();
    float sum = 0.f, sq = 0.f;
#pragma unroll
    for (int i = 0; i < 8; i++) { sum += s1[i]; sq += s2[i]; }
    const float mu = sum * (1.0f / D);
    const float var = sq * (1.0f / D) - mu * mu;
    const float rstd = rsqrtf(var + LNEPS);
    const float xv = (v - mu) * rstd * gamma[t] + beta[t];
    g_xn[(size_t)row * D + t] = xv;
    split_store(g_ah, g_al, (size_t)row * D + t, DN * xv);
    float c = xv * xv;
#pragma unroll
    for (int o = 16; o; o >>= 1) c += __shfl_down_sync(~0u, c, o);
    __syncthreads();
    if ((t & 31) == 0) s1[t >> 5] = c;
    __syncthreads();
    if (t == 0) {
        float d = 0.f;
#pragma unroll
        for (int i = 0; i < 8; i++) d += s1[i];
        g_diag[row] = d * (0.5f * DN * DN);
    }
}

// K1b: split proj to bf16 hi/lo
__global__ void __launch_bounds__(256) k_prep(const float* __restrict__ p) {
    const int i = blockIdx.x * 256 + threadIdx.x;
    split_store(g_pbh, g_pbl, i, p[i]);
}

// K1c: transpose xn -> vT (bf16 hi/lo), 32x32 tiles
__global__ void __launch_bounds__(256) k_vt() {
    const int b = blockIdx.z, s0 = blockIdx.x * 32, d0 = blockIdx.y * 32;
    __shared__ float sm[32][33];
    const int t = threadIdx.x;
#pragma unroll
    for (int it = 0; it < 4; it++) {
        const int idx = it * 256 + t, r = idx >> 5, c = idx & 31;
        sm[r][c] = g_xn[((size_t)b * S + s0 + r) * D + d0 + c];
    }
    __syncthreads();
#pragma unroll
    for (int it = 0; it < 4; it++) {
        const int idx = it * 256 + t, dr = idx >> 5, sc = idx & 31;
        split_store(g_vth, g_vtl, ((size_t)b * D + d0 + dr) * S + s0 + sc, sm[sc][dr]);
    }
}

// ============================================================
// Core mma.sync GEMM: D[128x128] = sum (Ah+Al)[128x256] @ (Bh+Bl)^T
// (bf16x3: AhBh + AhBl + AlBh, fp32 accum; K = 256 = 4 chunks of 64)
// MODE 0: pd = (DN*xn) @ proj^T       (+ rowmax partials)
// MODE 1: pctx[sk] = k^T @ v^T^T      (split-K partial over 256 s-rows)
// MODE 2: out = dinv * (q @ ctx^T^T)  (x8 head broadcast)
// ============================================================
template <int MODE>
__global__ void __launch_bounds__(256) k_mma(float* __restrict__ gout) {
    extern __shared__ char sm[];
    const u32 smb = s2u(sm);
    const int t = threadIdx.x, wid = t >> 5, lane = t & 31;

    int b, row0, col0, ldA, ldB, sk = 0;
    const __nv_bfloat16 *Ah, *Al, *Bh, *Bl;
    if constexpr (MODE == 0) {
        b = blockIdx.z; row0 = blockIdx.x * 128; col0 = blockIdx.y * 128;
        ldA = D; ldB = D;
        const size_t ao = ((size_t)b * S + row0) * D;
        Ah = g_ah + ao; Al = g_al + ao;
        const size_t bo = (size_t)col0 * D;
        Bh = g_pbh + bo; Bl = g_pbl + bo;
    } else if constexpr (MODE == 1) {
        b = blockIdx.z / SK; sk = blockIdx.z % SK;
        row0 = blockIdx.x * 128; col0 = blockIdx.y * 128;
        ldA = S; ldB = S;
        const size_t ao = ((size_t)b * M + row0) * S + sk * (S / SK);
        Ah = g_kth + ao; Al = g_ktl + ao;
        const size_t bo = ((size_t)b * D + col0) * S + sk * (S / SK);
        Bh = g_vth + bo; Bl = g_vtl + bo;
    } else {
        b = blockIdx.z; row0 = blockIdx.x * 128; col0 = blockIdx.y * 128;
        ldA = M; ldB = M;
        const size_t ao = ((size_t)b * S + row0) * M;
        Ah = g_qh + ao; Al = g_ql + ao;
        const size_t bo = ((size_t)b * D + col0) * M;
        Bh = g_cth + bo; Bl = g_ctl + bo;
    }

    // stage loader: 4 tiles x 128 rows x 128B via 16B cp.async (16 per thread)
    auto load_stage = [&](int ch, int st) {
        const __nv_bfloat16* srcs[4] = {Ah + ch * 64, Al + ch * 64,
                                        Bh + ch * 64, Bl + ch * 64};
#pragma unroll
        for (int it = 0; it < 16; it++) {
            const int idx = it * 256 + t;
            const int tile = idx >> 10, rem = idx & 1023;
            const int r = rem >> 3, c = rem & 7;
            const __nv_bfloat16* src =
                srcs[tile] + (size_t)r * ((tile < 2) ? ldA : ldB) + c * 8;
            const u32 dst = smb + st * STAGEB + tile * TILEB + r * TROW + c * 16;
            CP_ASYNC16(dst, src);
        }
        CP_COMMIT();
    };

    load_stage(0, 0);

    const int wm = wid >> 1, wn = wid & 1;     // warp tile 32(m) x 64(n)
    // ldmatrix per-lane offsets
    const u32 aoff = (u32)((lane & 15) * TROW + (lane >> 4) * 16);
    const u32 boff = (u32)(((lane & 7) + ((lane >> 4) & 1) * 8) * TROW +
                           ((lane >> 3) & 1) * 16);
    float acc[2][8][4] = {};

    for (int ch = 0; ch < 4; ch++) {
        const int st = ch & 1;
        if (ch < 3) {
            load_stage(ch + 1, st ^ 1);
            asm volatile("cp.async.wait_group 1;" ::: "memory");
        } else {
            asm volatile("cp.async.wait_group 0;" ::: "memory");
        }
        __syncthreads();
        const u32 sA = smb + st * STAGEB;
        const u32 sAh = sA, sAl = sA + TILEB, sBh = sA + 2 * TILEB, sBl = sA + 3 * TILEB;
#pragma unroll
        for (int ks = 0; ks < 4; ks++) {
            u32 ah[2][4], al[2][4], bh[4][4], bl[4][4];
#pragma unroll
            for (int mi = 0; mi < 2; mi++) {
                const u32 a = (u32)((wm * 32 + mi * 16) * TROW + ks * 32) + aoff;
                LDM4(ah[mi], sAh + a);
                LDM4(al[mi], sAl + a);
            }
#pragma unroll
            for (int g = 0; g < 4; g++) {
                const u32 a = (u32)((wn * 64 + g * 16) * TROW + ks * 32) + boff;
                LDM4(bh[g], sBh + a);
                LDM4(bl[g], sBl + a);
            }
#pragma unroll
            for (int mi = 0; mi < 2; mi++)
#pragma unroll
                for (int g = 0; g < 4; g++) {
                    MMA(acc[mi][2 * g],     ah[mi], bh[g][0], bh[g][1]);
                    MMA(acc[mi][2 * g + 1], ah[mi], bh[g][2], bh[g][3]);
                    MMA(acc[mi][2 * g],     ah[mi], bl[g][0], bl[g][1]);
                    MMA(acc[mi][2 * g + 1], ah[mi], bl[g][2], bl[g][3]);
                    MMA(acc[mi][2 * g],     al[mi], bh[g][0], bh[g][1]);
                    MMA(acc[mi][2 * g + 1], al[mi], bh[g][2], bh[g][3]);
                }
        }
        __syncthreads();
    }

    // Epilogue: fragments -> smem (fp32, NPAD stride) -> coalesced stores
    float* ep = (float*)sm;
#pragma unroll
    for (int mi = 0; mi < 2; mi++)
#pragma unroll
        for (int g = 0; g < 8; g++) {
            const int row = wm * 32 + mi * 16 + (lane >> 2);
            const int col = wn * 64 + g * 8 + (lane & 3) * 2;
            *(float2*)&ep[row * NPAD + col] =
                make_float2(acc[mi][g][0], acc[mi][g][1]);
            *(float2*)&ep[(row + 8) * NPAD + col] =
                make_float2(acc[mi][g][2], acc[mi][g][3]);
        }
    __syncthreads();

    const int row = t >> 1, half = t & 1, c0 = half * 64;
    const float* er = ep + row * NPAD + c0;
    if constexpr (MODE == 0) {
        float mx = -1e30f;
        const size_t o = ((size_t)b * S + row0 + row) * M + col0 + c0;
#pragma unroll
        for (int j = 0; j < 16; j++) {
            const float4 v = *(const float4*)(er + j * 4);
            mx = fmaxf(mx, fmaxf(fmaxf(v.x, v.y), fmaxf(v.z, v.w)));
            *(float4*)(g_pd + o + j * 4) = v;
        }
        mx = fmaxf(mx, __shfl_xor_sync(~0u, mx, 1));
        if (half == 0)
            g_pmax[(size_t)(b * S + row0 + row) * 2 + blockIdx.y] = mx;
    } else if constexpr (MODE == 1) {
        const size_t o =
            (((size_t)(b * SK + sk)) * M + row0 + row) * D + col0 + c0;
#pragma unroll
        for (int j = 0; j < 16; j++)
            *(float4*)(g_pctx + o + j * 4) = *(const float4*)(er + j * 4);
    } else {
        const float dv = g_dinv[b * S + row0 + row];
        const size_t o = ((size_t)b * H * S + row0 + row) * D + col0 + c0;
#pragma unroll
        for (int j = 0; j < 16; j++) {
            float4 v = *(const float4*)(er + j * 4);
            v.x *= dv; v.y *= dv; v.z *= dv; v.w *= dv;
#pragma unroll
            for (int h = 0; h < H; h++)
                *(float4*)(gout + o + (size_t)h * S * D + j * 4) = v;
        }
    }
}

// K3: rowmax from partials + batch max
__global__ void __launch_bounds__(256) k_maxred() {
    const int b = blockIdx.x, t = threadIdx.x;
    float bm = -1e30f;
    for (int s = t; s < S; s += 256) {
        const float rm = fmaxf(g_pmax[(size_t)(b * S + s) * 2],
                               g_pmax[(size_t)(b * S + s) * 2 + 1]);
        g_rowmax[b * S + s] = rm;
        bm = fmaxf(bm, rm);
    }
    __shared__ float red[8];
#pragma unroll
    for (int o = 16; o; o >>= 1) bm = fmaxf(bm, __shfl_xor_sync(~0u, bm, o));
    if ((t & 31) == 0) red[t >> 5] = bm;
    __syncthreads();
    if (t == 0) {
        float m2 = red[0];
#pragma unroll
        for (int i = 1; i < 8; i++) m2 = fmaxf(m2, red[i]);
        g_bmax[b] = m2;
    }
}

// K4: exp pass — q (split, [s,m]), k^T (split, [m,s]), ksum partials
__global__ void __launch_bounds__(256) k_kexp() {
    const int b = blockIdx.z, s0 = blockIdx.x * 32, m0 = blockIdx.y * 32;
    const int t = threadIdx.x;
    __shared__ float kk[32][33];
    __shared__ float fr[32], dm[32];
    if (t < 32) {
        const int s = s0 + t;
        const float rm = g_rowmax[b * S + s];
        dm[t] = g_diag[b * S + s] + rm;
        fr[t] = __expf(rm - g_bmax[b]);
    }
    __syncthreads();
#pragma unroll
    for (int it = 0; it < 4; it++) {
        const int idx = it * 256 + t, r = idx >> 5, c = idx & 31;
        const int s = s0 + r;
        const float pdv = g_pd[((size_t)b * S + s) * M + m0 + c];
        const float e = __expf(pdv - dm[r]);
        const float q = RATIO * e + RATIO * KEPS;
        const float k = RATIO * e * fr[r] + RATIO * KEPS;
        split_store(g_qh, g_ql, ((size_t)b * S + s) * M + m0 + c, q);
        kk[r][c] = k;
    }
    __syncthreads();
#pragma unroll
    for (int it = 0; it < 4; it++) {
        const int idx = it * 256 + t, mr = idx >> 5, sc = idx & 31;
        split_store(g_kth, g_ktl, ((size_t)b * M + m0 + mr) * S + s0 + sc,
                    kk[sc][mr]);
    }
    if (t < 32) {
        float s = 0.f;
#pragma unroll
        for (int i = 0; i < 32; i++) s += kk[i][t];
        g_pksum[((size_t)b * (S / 32) + (s0 >> 5)) * M + m0 + t] = s;
    }
}

// K4b: reduce ksum partials
__global__ void __launch_bounds__(256) k_ksumred() {
    const int b = blockIdx.x, t = threadIdx.x;
    float s = 0.f;
    for (int i = 0; i < S / 32; i++)
        s += g_pksum[((size_t)b * (S / 32) + i) * M + t];
    g_ksum[b * M + t] = s;
}

// K5b: reduce ctx partials + transpose + bf16 split -> ctx^T [d,m]
__global__ void __launch_bounds__(256) k_ctxred() {
    const int b = blockIdx.z, m0 = blockIdx.x * 32, d0 = blockIdx.y * 32;
    __shared__ float sm[32][33];
    const int t = threadIdx.x;
#pragma unroll
    for (int it = 0; it < 4; it++) {
        const int idx = it * 256 + t, mr = idx >> 5, dc = idx & 31;
        float s = 0.f;
#pragma unroll
        for (int sk = 0; sk < SK; sk++)
            s += g_pctx[(((size_t)(b * SK + sk)) * M + m0 + mr) * D + d0 + dc];
        sm[mr][dc] = s;
    }
    __syncthreads();
#pragma unroll
    for (int it = 0; it < 4; it++) {
        const int idx = it * 256 + t, dr = idx >> 5, mc = idx & 31;
        split_store(g_cth, g_ctl, ((size_t)b * D + d0 + dr) * M + m0 + mc,
                    sm[mc][dr]);
    }
}

// K6: dinv[s] = 1 / dot(q[s,:], ksum)  (one warp per row)
__global__ void __launch_bounds__(256) k_dinv() {
    __shared__ float ks[M];
    const int t = threadIdx.x, w = t >> 5, lane = t & 31;
    const int bid = blockIdx.x;
    const int b = bid / (S / 8);
    const int s = (bid % (S / 8)) * 8 + w;
    ks[t] = g_ksum[b * M + t];
    __syncthreads();
    const size_t qo = ((size_t)b * S + s) * M;
    float acc = 0.f;
#pragma unroll
    for (int i = 0; i < 8; i++) {
        const int m = lane + i * 32;
        const float q =
            __bfloat162float(g_qh[qo + m]) + __bfloat162float(g_ql[qo + m]);
        acc += q * ks[m];
    }
#pragma unroll
    for (int o = 16; o; o >>= 1) acc += __shfl_xor_sync(~0u, acc, o);
    if (lane == 0) g_dinv[b * S + s] = 1.0f / acc;
}

extern "C" void kernel_launch(void* const* d_in, const int* in_sizes, int n_in,
                              void* d_out, int out_size) {
    const float* x     = (const float*)d_in[0];
    const float* gamma = (const float*)d_in[1];
    const float* beta  = (const float*)d_in[2];
    const float* proj  = (const float*)d_in[3];
    float* out = (float*)d_out;
    (void)in_sizes; (void)n_in; (void)out_size;

    // Opt-in to >48KB dynamic smem. Host-side attribute set; not a stream op,
    // and it persists from the pre-capture correctness call.
    cudaFuncSetAttribute(k_mma<0>, cudaFuncAttributeMaxDynamicSharedMemorySize, SMEM_MMA);
    cudaFuncSetAttribute(k_mma<1>, cudaFuncAttributeMaxDynamicSharedMemorySize, SMEM_MMA);
    cudaFuncSetAttribute(k_mma<2>, cudaFuncAttributeMaxDynamicSharedMemorySize, SMEM_MMA);

    k_ln<<<B * S, 256>>>(x, gamma, beta);
    k_prep<<<M * D / 256, 256>>>(proj);
    k_vt<<<dim3(S / 32, D / 32, B), 256>>>();
    k_mma<0><<<dim3(S / 128, M / 128, B), 256, SMEM_MMA>>>(nullptr);
    k_maxred<<<B, 256>>>();
    k_kexp<<<dim3(S / 32, M / 32, B), 256>>>();
    k_ksumred<<<B, 256>>>();
    k_mma<1><<<dim3(M / 128, D / 128, B * SK), 256, SMEM_MMA>>>(nullptr);
    k_ctxred<<<dim3(M / 32, D / 32, B), 256>>>();
    k_dinv<<<B * S / 8, 256>>>();
    k_mma<2><<<dim3(S / 128, D / 128, B), 256, SMEM_MMA>>>(out);
}